// round 10
// baseline (speedup 1.0000x reference)
#include <cuda_runtime.h>
#include <math.h>
#include <stdint.h>

#define NNODES 10000
#define NEDGES 64000
#define IN_DIM 1247
#define KPAD   1280          /* IN_DIM padded to 40 k-tiles */
#define NKT0   40            /* KPAD/32 */
#define NKT1   32            /* 1024/32 */
#define NRT    79            /* ceil(10000/128) row tiles */
#define MPAD   (NRT * 128)   /* 10112 */
#define NH 4
#define DD0 256
#define DD1 8
#define OUTD 6
#define HD0 1024
#define HD1 32
#define NBIG 3104            /* 1024*3 + 32 (z2) */
#define NCT0 25              /* ceil(3104/128) col tiles */
#define L1W 96

// ------------------- scratch (device globals) --------------------------------
__device__ __align__(16) float g_colsum[IN_DIM];
__device__ __align__(16) float g_hA[(size_t)NRT * NKT0 * 4096];    /* A tiles, tf32 */
__device__ __align__(16) float g_WbigT[(size_t)NCT0 * NKT0 * 4096];/* B tiles, tf32 */
__device__ __align__(16) float g_WcatT[(size_t)1 * NKT1 * 4096];   /* layer1 B tiles */
__device__ __align__(16) float g_big[(size_t)NNODES * NBIG];       /* fs0|fd0|res0|z2 */
__device__ __align__(16) float g_x1A[(size_t)NRT * NKT1 * 4096];   /* x1 A tiles, tf32 */
__device__ __align__(16) float g_l1out[(size_t)NNODES * L1W];
__device__ __align__(16) float g_h3[NNODES * HD1];
__device__ __align__(16) float g_out1[NNODES * HD1];
__device__ float g_es2[NNODES * NH];
__device__ float g_ed2[NNODES * NH];
__device__ float g_lg0[NEDGES * NH];
__device__ float g_lg1[NEDGES * NH];
__device__ float g_lg2[NEDGES * NH];
__device__ float g_den[NNODES * NH];    /* softmax denominators (reused per layer) */
__device__ int   g_deg[NNODES];
__device__ int   g_fill[NNODES];
__device__ int   g_csr_off[NNODES + 1];
__device__ int   g_csr_edge[NEDGES];

__device__ __forceinline__ float lrelu(float x) { return x > 0.f ? x : 0.2f * x; }
__device__ __forceinline__ float to_tf32(float x) {
    float r; asm("cvt.rna.tf32.f32 %0, %1;" : "=f"(r) : "f"(x)); return r;
}
__device__ __forceinline__ uint32_t fau(float x) { return __float_as_uint(x); }
// packed-tile element offset for (row r in tile, local k)
__device__ __forceinline__ int tileOff(int r, int kl) {
    int ck = ((kl & 3) << 3) | (kl >> 2);
    int chunk = (ck >> 2) ^ (r & 7);
    return (r << 5) + (chunk << 2) + (ck & 3);
}
__device__ __forceinline__ void cp16(uint32_t s, const float* g) {
    asm volatile("cp.async.cg.shared.global [%0], [%1], 16;" :: "r"(s), "l"(g));
}

// ------------------- preprocessing ------------------------------------------
// atomic-free column sums: thread j loops all rows (coalesced across j)
__global__ void colsumKernel(const float* __restrict__ f) {
    int j = blockIdx.x * 128 + threadIdx.x;
    if (j >= IN_DIM) return;
    float s0 = 0.f, s1 = 0.f, s2 = 0.f, s3 = 0.f;
    for (int i = 0; i < NNODES; i += 4) {
        s0 += f[(size_t)i * IN_DIM + j];
        s1 += f[(size_t)(i + 1) * IN_DIM + j];
        s2 += f[(size_t)(i + 2) * IN_DIM + j];
        s3 += f[(size_t)(i + 3) * IN_DIM + j];
    }
    g_colsum[j] = (s0 + s1) + (s2 + s3);
}

__global__ void preprocessKernel(const float* __restrict__ f,
                                 const float* __restrict__ tm,
                                 const float* __restrict__ am,
                                 const float* __restrict__ vm) {
    __shared__ float sh[IN_DIM];
    __shared__ float red[8];
    int n = blockIdx.x;            // 0..MPAD-1
    int t = threadIdx.x;
    int r = n & 127, rt = n >> 7;
    float* base = g_hA + ((size_t)rt * NKT0 << 12);
    if (n >= NNODES) {
        for (int j = t; j < KPAD; j += 256)
            base[((j >> 5) << 12) + tileOff(r, j & 31)] = 0.f;
        return;
    }
    const float* row = f + (size_t)n * IN_DIM;
    const float invN = 1.f / (float)NNODES;
    float s = 0.f;
    for (int j = t; j < IN_DIM; j += 256) {
        float v = row[j];
        v = (v == 0.f) ? (0.5f * g_colsum[j] * invN) : v;
        sh[j] = v;
        s += fabsf(v);
    }
    for (int off = 16; off; off >>= 1) s += __shfl_down_sync(0xffffffffu, s, off);
    if ((t & 31) == 0) red[t >> 5] = s;
    __syncthreads();
    if (t == 0) {
        float tot = 0.f;
        for (int w = 0; w < 8; w++) tot += red[w];
        red[0] = 1.f / fmaxf(tot, 1e-12f);
    }
    __syncthreads();
    float inv = red[0];
    for (int j = t; j < KPAD; j += 256) {
        float v = 0.f;
        if (j < IN_DIM) v = to_tf32(sh[j] * inv * (tm[j] + am[j] + vm[j]));
        base[((j >> 5) << 12) + tileOff(r, j & 31)] = v;
    }
}

// g_WbigT: cols [Wl0|Wr0|Wres0|W2packed|0], packed tile images, tf32
__global__ void packWbigTKernel(const float* __restrict__ Wl0,
                                const float* __restrict__ Wr0,
                                const float* __restrict__ Wres0,
                                const float* __restrict__ W2) {
    int i = blockIdx.x * 256 + threadIdx.x;
    if (i >= NCT0 * NKT0 * 4096) return;
    int ct = i / (NKT0 * 4096);
    int rem = i % (NKT0 * 4096);
    int kt = rem >> 12;
    int p = rem & 4095;
    int r = p >> 5, pos = p & 31;
    int chunk = (pos >> 2) ^ (r & 7);
    int ck = (chunk << 2) | (pos & 3);
    int kl = ((ck & 7) << 2) | (ck >> 3);
    int k = kt * 32 + kl;
    int n = ct * 128 + r;
    float v = 0.f;
    if (k < IN_DIM) {
        if (n < HD0) v = Wl0[(size_t)k * HD0 + n];
        else if (n < 2 * HD0) v = Wr0[(size_t)k * HD0 + (n - HD0)];
        else if (n < 3 * HD0) v = Wres0[(size_t)k * HD0 + (n - 2 * HD0)];
        else if (n < 3 * HD0 + HD1) {
            int cc = n - 3 * HD0;
            v = W2[((size_t)(cc >> 3) * IN_DIM + k) * DD1 + (cc & 7)];
        }
    }
    g_WbigT[i] = to_tf32(v);
}

// g_WcatT: cols [Wl1|Wr1|Wres1|0], K=1024, tf32
__global__ void packWcatTKernel(const float* __restrict__ Wl1,
                                const float* __restrict__ Wr1,
                                const float* __restrict__ Wres1) {
    int i = blockIdx.x * 256 + threadIdx.x;
    if (i >= NKT1 * 4096) return;
    int kt = i >> 12;
    int p = i & 4095;
    int r = p >> 5, pos = p & 31;
    int chunk = (pos >> 2) ^ (r & 7);
    int ck = (chunk << 2) | (pos & 3);
    int kl = ((ck & 7) << 2) | (ck >> 3);
    int k = kt * 32 + kl;
    int n = r;
    float v = 0.f;
    if (n < HD1) v = Wl1[(size_t)k * HD1 + n];
    else if (n < 2 * HD1) v = Wr1[(size_t)k * HD1 + (n - HD1)];
    else if (n < L1W) v = Wres1[(size_t)k * HD1 + (n - 2 * HD1)];
    g_WcatT[i] = to_tf32(v);
}

// ------------------- CSR build ----------------------------------------------
__global__ void zeroKernel() {
    int i = blockIdx.x * 256 + threadIdx.x;
    if (i < NNODES) { g_deg[i] = 0; g_fill[i] = 0; }
}

__global__ void histKernel(const int* __restrict__ dst) {
    int e = blockIdx.x * 256 + threadIdx.x;
    if (e < NEDGES) atomicAdd(&g_deg[dst[e]], 1);
}

__global__ void scanKernel() {
    __shared__ int sums[1024];
    const int CH = (NNODES + 1023) / 1024;
    int t = threadIdx.x;
    int base = t * CH;
    int local[CH];
    int s = 0;
    for (int i = 0; i < CH; i++) {
        int v = (base + i < NNODES) ? g_deg[base + i] : 0;
        local[i] = s;
        s += v;
    }
    sums[t] = s;
    __syncthreads();
    for (int off = 1; off < 1024; off <<= 1) {
        int v = (t >= off) ? sums[t - off] : 0;
        __syncthreads();
        sums[t] += v;
        __syncthreads();
    }
    int excl = (t == 0) ? 0 : sums[t - 1];
    for (int i = 0; i < CH; i++)
        if (base + i < NNODES) g_csr_off[base + i] = excl + local[i];
    if (t == 1023) g_csr_off[NNODES] = sums[1023];
}

__global__ void fillCsrKernel(const int* __restrict__ dst) {
    int e = blockIdx.x * 256 + threadIdx.x;
    if (e >= NEDGES) return;
    int d = dst[e];
    int pos = atomicAdd(&g_fill[d], 1);
    g_csr_edge[g_csr_off[d] + pos] = e;
}

// ------------------- TF32 tensor GEMM on pre-packed tiles (R6, proven) -------
#define GEMM_SMEM (16384 * sizeof(float))

__global__ __launch_bounds__(256, 2) void tf32GemmKernel(
    const float* __restrict__ Apack, const float* __restrict__ Bpack,
    int nKt, float* __restrict__ C, int ldc, int Mrows, int Ncols) {
    extern __shared__ float sm[];
    int tid = threadIdx.x;
    int lane = tid & 31;
    int w = tid >> 5;
    int wm = w & 1, wn = w >> 1;
    int g = lane >> 2, tg = lane & 3;
    int r0 = blockIdx.x * 128, c0 = blockIdx.y * 128;

    const float* gA = Apack + ((size_t)blockIdx.x * nKt << 12);
    const float* gB = Bpack + ((size_t)blockIdx.y * nKt << 12);
    uint32_t sbase = (uint32_t)__cvta_generic_to_shared(sm);
    uint32_t sA[2] = {sbase, sbase + 16384u};
    uint32_t sB[2] = {sbase + 32768u, sbase + 49152u};

    float acc[4][4][4];
#pragma unroll
    for (int i = 0; i < 4; i++)
#pragma unroll
        for (int j = 0; j < 4; j++)
#pragma unroll
            for (int r = 0; r < 4; r++) acc[i][j][r] = 0.f;

#pragma unroll
    for (int s = 0; s < 4; s++) {
        int i = s * 256 + tid;
        cp16(sA[0] + i * 16, gA + i * 4);
        cp16(sB[0] + i * 16, gB + i * 4);
    }
    asm volatile("cp.async.commit_group;" ::: "memory");

    for (int kt = 0; kt < nKt; kt++) {
        int buf = kt & 1;
        bool hasNext = (kt + 1) < nKt;
        if (hasNext) {
            const float* nA = gA + ((size_t)(kt + 1) << 12);
            const float* nB = gB + ((size_t)(kt + 1) << 12);
            int nb = buf ^ 1;
#pragma unroll
            for (int s = 0; s < 4; s++) {
                int i = s * 256 + tid;
                cp16(sA[nb] + i * 16, nA + i * 4);
                cp16(sB[nb] + i * 16, nB + i * 4);
            }
            asm volatile("cp.async.commit_group;" ::: "memory");
            asm volatile("cp.async.wait_group 1;" ::: "memory");
        } else {
            asm volatile("cp.async.wait_group 0;" ::: "memory");
        }
        __syncthreads();

        const float* As = sm + (buf ? 4096 : 0);
        const float* Bs = sm + 8192 + (buf ? 4096 : 0);
#pragma unroll
        for (int half = 0; half < 2; half++) {
            int chunk = ((tg << 1) + half) ^ g;
            int coff = chunk << 2;
            float4 Af0[4], Af1[4], Bf[4];
#pragma unroll
            for (int mf = 0; mf < 4; mf++) {
                int r = wm * 64 + mf * 16 + g;
                Af0[mf] = *(const float4*)(As + (r << 5) + coff);
                Af1[mf] = *(const float4*)(As + ((r + 8) << 5) + coff);
            }
#pragma unroll
            for (int nf = 0; nf < 4; nf++) {
                int cc = wn * 32 + nf * 8 + g;
                Bf[nf] = *(const float4*)(Bs + (cc << 5) + coff);
            }
#pragma unroll
            for (int ks2 = 0; ks2 < 2; ks2++) {
#pragma unroll
                for (int mf = 0; mf < 4; mf++) {
                    uint32_t a0, a1, a2, a3;
                    if (ks2 == 0) {
                        a0 = fau(Af0[mf].x); a1 = fau(Af1[mf].x);
                        a2 = fau(Af0[mf].y); a3 = fau(Af1[mf].y);
                    } else {
                        a0 = fau(Af0[mf].z); a1 = fau(Af1[mf].z);
                        a2 = fau(Af0[mf].w); a3 = fau(Af1[mf].w);
                    }
#pragma unroll
                    for (int nf = 0; nf < 4; nf++) {
                        uint32_t b0 = (ks2 == 0) ? fau(Bf[nf].x) : fau(Bf[nf].z);
                        uint32_t b1 = (ks2 == 0) ? fau(Bf[nf].y) : fau(Bf[nf].w);
                        asm volatile(
                            "mma.sync.aligned.m16n8k8.row.col.f32.tf32.tf32.f32 "
                            "{%0,%1,%2,%3}, {%4,%5,%6,%7}, {%8,%9}, {%0,%1,%2,%3};"
                            : "+f"(acc[mf][nf][0]), "+f"(acc[mf][nf][1]),
                              "+f"(acc[mf][nf][2]), "+f"(acc[mf][nf][3])
                            : "r"(a0), "r"(a1), "r"(a2), "r"(a3),
                              "r"(b0), "r"(b1));
                    }
                }
            }
        }
        __syncthreads();
    }

#pragma unroll
    for (int mf = 0; mf < 4; mf++) {
        int rA = r0 + wm * 64 + mf * 16 + g;
        int rB = rA + 8;
#pragma unroll
        for (int nf = 0; nf < 4; nf++) {
            int gc = c0 + wn * 32 + nf * 8 + tg * 2;
            if (gc < Ncols) {
                if (rA < Mrows) C[(size_t)rA * ldc + gc] = acc[mf][nf][0];
                if (rB < Mrows) C[(size_t)rB * ldc + gc] = acc[mf][nf][2];
            }
            if (gc + 1 < Ncols) {
                if (rA < Mrows) C[(size_t)rA * ldc + gc + 1] = acc[mf][nf][1];
                if (rB < Mrows) C[(size_t)rB * ldc + gc + 1] = acc[mf][nf][3];
            }
        }
    }
}

// ------------------- gat_inner (h3) ------------------------------------------
__global__ void innerNodeTermsKernel(const float* __restrict__ a2) {
    int idx = blockIdx.x * 256 + threadIdx.x;
    if (idx >= NNODES * NH) return;
    int n = idx / NH, h = idx % NH;
    const float* z = g_big + (size_t)n * NBIG + 3 * HD0 + h * DD1;
    float es = 0.f, ed = 0.f;
#pragma unroll
    for (int o = 0; o < DD1; o++) {
        es = fmaf(z[o], a2[h * 2 * DD1 + o], es);
        ed = fmaf(z[o], a2[h * 2 * DD1 + DD1 + o], ed);
    }
    g_es2[idx] = es;
    g_ed2[idx] = ed;
}

// fused: compute inner logits + segment softmax (unnormalized) + den
__global__ void innerSoftmaxKernel(const int* __restrict__ src) {
    int idx = blockIdx.x * 256 + threadIdx.x;
    if (idx >= NNODES * NH) return;
    int n = idx / NH, h = idx % NH;
    int s = g_csr_off[n], t = g_csr_off[n + 1];
    float edv = g_ed2[idx];                 // dst term constant per segment
    float m = -1e30f;
    for (int p = s; p < t; p++) {
        int e = g_csr_edge[p];
        float l = lrelu(g_es2[src[e] * NH + h] + edv);
        g_lg2[e * NH + h] = l;
        m = fmaxf(m, l);
    }
    float den = 0.f;
    for (int p = s; p < t; p++) {
        int a = g_csr_edge[p] * NH + h;
        float pv = __expf(g_lg2[a] - m);
        den += pv;
        g_lg2[a] = pv;
    }
    g_den[idx] = fmaxf(den, 1e-9f);
}

// segment softmax over precomputed logits: leaves p unnormalized, writes den
__global__ void segSoftmaxKernel(float* __restrict__ lg) {
    int idx = blockIdx.x * 256 + threadIdx.x;
    if (idx >= NNODES * NH) return;
    int n = idx / NH, h = idx % NH;
    int s = g_csr_off[n], t = g_csr_off[n + 1];
    float m = -1e30f;
    for (int p = s; p < t; p++) m = fmaxf(m, lg[g_csr_edge[p] * NH + h]);
    float den = 0.f;
    for (int p = s; p < t; p++) {
        int a = g_csr_edge[p] * NH + h;
        float pv = __expf(lg[a] - m);
        den += pv;
        lg[a] = pv;
    }
    g_den[idx] = fmaxf(den, 1e-9f);
}

// warp-per-node aggregation for 32-wide values; divides by den
__global__ void aggSmallKernel(const float* __restrict__ vals, int vstride,
                               const float* __restrict__ lg,
                               const int* __restrict__ src,
                               const float* __restrict__ res, int rstride,
                               const float* __restrict__ bias,
                               float* __restrict__ out, int doRelu) {
    int w = (blockIdx.x * blockDim.x + threadIdx.x) >> 5;
    int lane = threadIdx.x & 31;
    if (w >= NNODES) return;
    int h = lane >> 3;
    int s = g_csr_off[w], t = g_csr_off[w + 1];
    float acc = 0.f;
    for (int p = s; p < t; p++) {
        int e = g_csr_edge[p];
        acc = fmaf(lg[e * NH + h], vals[(size_t)src[e] * vstride + lane], acc);
    }
    acc *= 1.f / g_den[w * NH + h];
    if (res) acc += res[(size_t)w * rstride + lane] + bias[lane];
    if (doRelu) acc = fmaxf(acc, 0.f);
    out[w * HD1 + lane] = acc;
}

// ------------------- gatv2 layer 0 (D=256) ------------------------------------
__global__ void gatv2EdgeLogits0Kernel(const int* __restrict__ src,
                                       const int* __restrict__ dst,
                                       const float* __restrict__ a0) {
    int e = blockIdx.x;
    int t = threadIdx.x;  // 128
    const float4* fs = (const float4*)(g_big + (size_t)src[e] * NBIG);
    const float4* fd = (const float4*)(g_big + (size_t)dst[e] * NBIG + HD0);
    const float4* a4 = (const float4*)a0;
    float partial = 0.f;
#pragma unroll
    for (int q = 0; q < 2; q++) {
        int i4 = t * 2 + q;
        float4 u = fs[i4], v = fd[i4], w = a4[i4];
        partial = fmaf(lrelu(u.x + v.x), w.x, partial);
        partial = fmaf(lrelu(u.y + v.y), w.y, partial);
        partial = fmaf(lrelu(u.z + v.z), w.z, partial);
        partial = fmaf(lrelu(u.w + v.w), w.w, partial);
    }
    for (int off = 16; off; off >>= 1)
        partial += __shfl_down_sync(0xffffffffu, partial, off);
    if ((t & 31) == 0) g_lg0[e * NH + (t >> 5)] = partial;
}

// aggregate layer-0 (unnormalized p, divide by den), residual+bias+relu;
// emit x1 as packed tf32 tiles
__global__ void gatv2Agg0Kernel(const int* __restrict__ src,
                                const float* __restrict__ b0) {
    int n = blockIdx.x;            // 0..MPAD-1
    int t = threadIdx.x;           // 256; 4 consecutive k each
    int r = n & 127, rt = n >> 7;
    float* base = g_x1A + ((size_t)rt * NKT1 << 12);
    if (n >= NNODES) {
#pragma unroll
        for (int q = 0; q < 4; q++) {
            int k = t * 4 + q;
            base[((k >> 5) << 12) + tileOff(r, k & 31)] = 0.f;
        }
        return;
    }
    int h = t >> 6;
    int s = g_csr_off[n], e1 = g_csr_off[n + 1];
    float4 acc = make_float4(0.f, 0.f, 0.f, 0.f);
    for (int p = s; p < e1; p++) {
        int e = g_csr_edge[p];
        float a = g_lg0[e * NH + h];
        float4 v = ((const float4*)(g_big + (size_t)src[e] * NBIG))[t];
        acc.x = fmaf(a, v.x, acc.x);
        acc.y = fmaf(a, v.y, acc.y);
        acc.z = fmaf(a, v.z, acc.z);
        acc.w = fmaf(a, v.w, acc.w);
    }
    float invd = 1.f / g_den[n * NH + h];
    float4 rr = ((const float4*)(g_big + (size_t)n * NBIG + 2 * HD0))[t];
    float4 bb = ((const float4*)b0)[t];
    float o[4];
    o[0] = fmaxf(acc.x * invd + rr.x + bb.x, 0.f);
    o[1] = fmaxf(acc.y * invd + rr.y + bb.y, 0.f);
    o[2] = fmaxf(acc.z * invd + rr.z + bb.z, 0.f);
    o[3] = fmaxf(acc.w * invd + rr.w + bb.w, 0.f);
#pragma unroll
    for (int q = 0; q < 4; q++) {
        int k = t * 4 + q;
        base[((k >> 5) << 12) + tileOff(r, k & 31)] = to_tf32(o[q]);
    }
}

// ------------------- gatv2 layer 1 (D=8) --------------------------------------
__global__ void gatv2EdgeLogits1Kernel(const int* __restrict__ src,
                                       const int* __restrict__ dst,
                                       const float* __restrict__ a1) {
    int w = (blockIdx.x * blockDim.x + threadIdx.x) >> 5;
    int lane = threadIdx.x & 31;
    if (w >= NEDGES) return;
    float x = g_l1out[(size_t)src[w] * L1W + lane] +
              g_l1out[(size_t)dst[w] * L1W + HD1 + lane];
    float p = lrelu(x) * a1[lane];
    p += __shfl_down_sync(0xffffffffu, p, 4, 8);
    p += __shfl_down_sync(0xffffffffu, p, 2, 8);
    p += __shfl_down_sync(0xffffffffu, p, 1, 8);
    if ((lane & 7) == 0) g_lg1[w * NH + (lane >> 3)] = p;
}

// ------------------- final linear ---------------------------------------------
__global__ void finalLinearKernel(const float* __restrict__ Wlin,
                                  const float* __restrict__ blin,
                                  float* __restrict__ out) {
    int n = blockIdx.x * 256 + threadIdx.x;
    if (n >= NNODES) return;
    float acc[OUTD];
#pragma unroll
    for (int c = 0; c < OUTD; c++) acc[c] = blin[c];
#pragma unroll 4
    for (int j = 0; j < HD1; j++) {
        float v = g_h3[n * HD1 + j];
#pragma unroll
        for (int c = 0; c < OUTD; c++) acc[c] = fmaf(v, Wlin[j * OUTD + c], acc[c]);
    }
#pragma unroll 4
    for (int j = 0; j < HD1; j++) {
        float v = g_out1[n * HD1 + j];
#pragma unroll
        for (int c = 0; c < OUTD; c++)
            acc[c] = fmaf(v, Wlin[(HD1 + j) * OUTD + c], acc[c]);
    }
#pragma unroll
    for (int c = 0; c < OUTD; c++) out[n * OUTD + c] = acc[c];
}

// ------------------- launch ---------------------------------------------------
extern "C" void kernel_launch(void* const* d_in, const int* in_sizes, int n_in,
                              void* d_out, int out_size) {
    const float* features = (const float*)d_in[0];
    const int* src = (const int*)d_in[1];
    const int* dst = (const int*)d_in[2];
    const float* textMask = (const float*)d_in[3];
    const float* audioMask = (const float*)d_in[4];
    const float* videoMask = (const float*)d_in[5];
    const float* W2 = (const float*)d_in[6];
    const float* a2 = (const float*)d_in[7];
    const float* Wl0 = (const float*)d_in[8];
    const float* Wr0 = (const float*)d_in[9];
    const float* a0 = (const float*)d_in[10];
    const float* Wres0 = (const float*)d_in[11];
    const float* b0 = (const float*)d_in[12];
    const float* Wl1 = (const float*)d_in[13];
    const float* Wr1 = (const float*)d_in[14];
    const float* a1 = (const float*)d_in[15];
    const float* Wres1 = (const float*)d_in[16];
    const float* b1 = (const float*)d_in[17];
    const float* Wlin = (const float*)d_in[18];
    const float* blin = (const float*)d_in[19];
    float* out = (float*)d_out;

    float *p_hA, *p_WbigT, *p_WcatT, *p_big, *p_x1A, *p_l1out;
    float *p_lg0, *p_lg1, *p_lg2, *p_h3, *p_out1;
    cudaGetSymbolAddress((void**)&p_hA, g_hA);
    cudaGetSymbolAddress((void**)&p_WbigT, g_WbigT);
    cudaGetSymbolAddress((void**)&p_WcatT, g_WcatT);
    cudaGetSymbolAddress((void**)&p_big, g_big);
    cudaGetSymbolAddress((void**)&p_x1A, g_x1A);
    cudaGetSymbolAddress((void**)&p_l1out, g_l1out);
    cudaGetSymbolAddress((void**)&p_lg0, g_lg0);
    cudaGetSymbolAddress((void**)&p_lg1, g_lg1);
    cudaGetSymbolAddress((void**)&p_lg2, g_lg2);
    cudaGetSymbolAddress((void**)&p_h3, g_h3);
    cudaGetSymbolAddress((void**)&p_out1, g_out1);

    cudaFuncSetAttribute(tf32GemmKernel,
                         cudaFuncAttributeMaxDynamicSharedMemorySize,
                         (int)GEMM_SMEM);

    // 1-3) preprocessing (launch #4 = big GEMM for the ncu capture slot)
    colsumKernel<<<(IN_DIM + 127) / 128, 128>>>(features);
    preprocessKernel<<<MPAD, 256>>>(features, textMask, audioMask, videoMask);
    packWbigTKernel<<<(NCT0 * NKT0 * 4096 + 255) / 256, 256>>>(Wl0, Wr0, Wres0, W2);

    // 4) fused big GEMM: [10112 x 1280] x [1280 x 3200] -> g_big [10000 x 3104]
    {
        dim3 g(NRT, NCT0);
        tf32GemmKernel<<<g, 256, GEMM_SMEM>>>(p_hA, p_WbigT, NKT0, p_big, NBIG,
                                              NNODES, NBIG);
    }

    // 5+) layer-1 weight pack + CSR build
    packWcatTKernel<<<(NKT1 * 4096 + 255) / 256, 256>>>(Wl1, Wr1, Wres1);
    zeroKernel<<<(NNODES + 255) / 256, 256>>>();
    histKernel<<<(NEDGES + 255) / 256, 256>>>(dst);
    scanKernel<<<1, 1024>>>();
    fillCsrKernel<<<(NEDGES + 255) / 256, 256>>>(dst);

    // gat_inner -> h3 (z2 = g_big cols 3072..3103)
    innerNodeTermsKernel<<<(NNODES * NH + 255) / 256, 256>>>(a2);
    innerSoftmaxKernel<<<(NNODES * NH + 255) / 256, 256>>>(src);
    aggSmallKernel<<<(NNODES * 32 + 255) / 256, 256>>>(p_big + 3 * HD0, NBIG, p_lg2,
                                                       src, (const float*)0, 0,
                                                       (const float*)0, p_h3, 0);

    // gatv2 layer 0 -> x1 (packed tiles)
    gatv2EdgeLogits0Kernel<<<NEDGES, 128>>>(src, dst, a0);
    segSoftmaxKernel<<<(NNODES * NH + 255) / 256, 256>>>(p_lg0);
    gatv2Agg0Kernel<<<MPAD, 256>>>(src, b0);

    // layer-1 projections: [10112 x 1024] x [1024 x 128] -> g_l1out [10000 x 96]
    {
        dim3 g(NRT, 1);
        tf32GemmKernel<<<g, 256, GEMM_SMEM>>>(p_x1A, p_WcatT, NKT1, p_l1out, L1W,
                                              NNODES, L1W);
    }

    // gatv2 layer 1 -> out1
    gatv2EdgeLogits1Kernel<<<(NEDGES * 32 + 255) / 256, 256>>>(src, dst, a1);
    segSoftmaxKernel<<<(NNODES * NH + 255) / 256, 256>>>(p_lg1);
    aggSmallKernel<<<(NNODES * 32 + 255) / 256, 256>>>(p_l1out, L1W, p_lg1, src,
                                                       p_l1out + 2 * HD1, L1W, b1,
                                                       p_out1, 1);

    // final linear
    finalLinearKernel<<<(NNODES + 255) / 256, 256>>>(Wlin, blin, out);
}

// round 11
// speedup vs baseline: 1.3582x; 1.3582x over previous
#include <cuda_runtime.h>
#include <math.h>
#include <stdint.h>

#define NNODES 10000
#define NEDGES 64000
#define IN_DIM 1247
#define KPAD   1280          /* IN_DIM padded to 40 k-tiles */
#define NKT0   40            /* KPAD/32 */
#define NKT1   32            /* 1024/32 */
#define NRT    79            /* ceil(10000/128) row tiles */
#define MPAD   (NRT * 128)   /* 10112 */
#define NH 4
#define DD0 256
#define DD1 8
#define OUTD 6
#define HD0 1024
#define HD1 32
#define NBIG 3104            /* 1024*3 + 32 (z2) */
#define NCT0 25              /* ceil(3104/128) col tiles */
#define L1W 96

// ------------------- scratch (device globals) --------------------------------
__device__ __align__(16) float g_colsum[IN_DIM];
__device__ __align__(16) float g_hA[(size_t)NRT * NKT0 * 4096];    /* A tiles, tf32 */
__device__ __align__(16) float g_WbigT[(size_t)NCT0 * NKT0 * 4096];/* B tiles, tf32 */
__device__ __align__(16) float g_WcatT[(size_t)1 * NKT1 * 4096];   /* layer1 B tiles */
__device__ __align__(16) float g_big[(size_t)NNODES * NBIG];       /* fs0|fd0|res0|z2 */
__device__ __align__(16) float g_x1A[(size_t)NRT * NKT1 * 4096];   /* x1 A tiles, tf32 */
__device__ __align__(16) float g_l1out[(size_t)NNODES * L1W];
__device__ __align__(16) float g_h3[NNODES * HD1];
__device__ __align__(16) float g_out1[NNODES * HD1];
__device__ float g_es2[NNODES * NH];
__device__ float g_ed2[NNODES * NH];
__device__ float g_lg0[NEDGES * NH];
__device__ float g_lg1[NEDGES * NH];
__device__ float g_lg2[NEDGES * NH];
__device__ float g_den[NNODES * NH];    /* softmax denominators (reused per layer) */
__device__ int   g_deg[NNODES];
__device__ int   g_fill[NNODES];
__device__ int   g_csr_off[NNODES + 1];
__device__ int   g_csr_edge[NEDGES];

__device__ __forceinline__ float lrelu(float x) { return x > 0.f ? x : 0.2f * x; }
__device__ __forceinline__ float to_tf32(float x) {
    float r; asm("cvt.rna.tf32.f32 %0, %1;" : "=f"(r) : "f"(x)); return r;
}
__device__ __forceinline__ uint32_t fau(float x) { return __float_as_uint(x); }
// packed-tile element offset for (row r in tile, local k)
__device__ __forceinline__ int tileOff(int r, int kl) {
    int ck = ((kl & 3) << 3) | (kl >> 2);
    int chunk = (ck >> 2) ^ (r & 7);
    return (r << 5) + (chunk << 2) + (ck & 3);
}
__device__ __forceinline__ void cp16(uint32_t s, const float* g) {
    asm volatile("cp.async.cg.shared.global [%0], [%1], 16;" :: "r"(s), "l"(g));
}

// ------------------- preprocessing ------------------------------------------
// one-launch, no-zero, no-atomic column sums.
// block b owns columns [b*32, b*32+32); 8 row-lanes x 32 col-lanes;
// warp reads a 128B coalesced row segment; smem reduce across row-lanes.
__global__ void colsumKernel(const float* __restrict__ f) {
    __shared__ float sacc[8][33];
    int cx = threadIdx.x & 31, ry = threadIdx.x >> 5;
    int j = blockIdx.x * 32 + cx;
    float s0 = 0.f, s1 = 0.f, s2 = 0.f, s3 = 0.f;
    if (j < IN_DIM) {
        for (int i = ry; i + 24 < NNODES; i += 32) {
            s0 += f[(size_t)i * IN_DIM + j];
            s1 += f[(size_t)(i + 8) * IN_DIM + j];
            s2 += f[(size_t)(i + 16) * IN_DIM + j];
            s3 += f[(size_t)(i + 24) * IN_DIM + j];
        }
        // NNODES % 32 == 16: tail rows 9984+ry, 9992+ry
        int tail = (NNODES & ~31) + ry;
        if (tail < NNODES) s0 += f[(size_t)tail * IN_DIM + j];
        if (tail + 8 < NNODES) s1 += f[(size_t)(tail + 8) * IN_DIM + j];
    }
    sacc[ry][cx] = (s0 + s1) + (s2 + s3);
    __syncthreads();
    if (ry == 0 && j < IN_DIM) {
        float tot = 0.f;
#pragma unroll
        for (int q = 0; q < 8; q++) tot += sacc[q][cx];
        g_colsum[j] = tot;
    }
}

__global__ void preprocessKernel(const float* __restrict__ f,
                                 const float* __restrict__ tm,
                                 const float* __restrict__ am,
                                 const float* __restrict__ vm) {
    __shared__ float sh[IN_DIM];
    __shared__ float red[8];
    int n = blockIdx.x;            // 0..MPAD-1
    int t = threadIdx.x;
    int r = n & 127, rt = n >> 7;
    float* base = g_hA + ((size_t)rt * NKT0 << 12);
    if (n >= NNODES) {
        for (int j = t; j < KPAD; j += 256)
            base[((j >> 5) << 12) + tileOff(r, j & 31)] = 0.f;
        return;
    }
    const float* row = f + (size_t)n * IN_DIM;
    const float invN = 1.f / (float)NNODES;
    float s = 0.f;
    for (int j = t; j < IN_DIM; j += 256) {
        float v = row[j];
        v = (v == 0.f) ? (0.5f * g_colsum[j] * invN) : v;
        sh[j] = v;
        s += fabsf(v);
    }
    for (int off = 16; off; off >>= 1) s += __shfl_down_sync(0xffffffffu, s, off);
    if ((t & 31) == 0) red[t >> 5] = s;
    __syncthreads();
    if (t == 0) {
        float tot = 0.f;
        for (int w = 0; w < 8; w++) tot += red[w];
        red[0] = 1.f / fmaxf(tot, 1e-12f);
    }
    __syncthreads();
    float inv = red[0];
    for (int j = t; j < KPAD; j += 256) {
        float v = 0.f;
        if (j < IN_DIM) v = to_tf32(sh[j] * inv * (tm[j] + am[j] + vm[j]));
        base[((j >> 5) << 12) + tileOff(r, j & 31)] = v;
    }
}

// g_WbigT: cols [Wl0|Wr0|Wres0|W2packed|0], packed tile images, tf32
__global__ void packWbigTKernel(const float* __restrict__ Wl0,
                                const float* __restrict__ Wr0,
                                const float* __restrict__ Wres0,
                                const float* __restrict__ W2) {
    int i = blockIdx.x * 256 + threadIdx.x;
    if (i >= NCT0 * NKT0 * 4096) return;
    int ct = i / (NKT0 * 4096);
    int rem = i % (NKT0 * 4096);
    int kt = rem >> 12;
    int p = rem & 4095;
    int r = p >> 5, pos = p & 31;
    int chunk = (pos >> 2) ^ (r & 7);
    int ck = (chunk << 2) | (pos & 3);
    int kl = ((ck & 7) << 2) | (ck >> 3);
    int k = kt * 32 + kl;
    int n = ct * 128 + r;
    float v = 0.f;
    if (k < IN_DIM) {
        if (n < HD0) v = Wl0[(size_t)k * HD0 + n];
        else if (n < 2 * HD0) v = Wr0[(size_t)k * HD0 + (n - HD0)];
        else if (n < 3 * HD0) v = Wres0[(size_t)k * HD0 + (n - 2 * HD0)];
        else if (n < 3 * HD0 + HD1) {
            int cc = n - 3 * HD0;
            v = W2[((size_t)(cc >> 3) * IN_DIM + k) * DD1 + (cc & 7)];
        }
    }
    g_WbigT[i] = to_tf32(v);
}

// g_WcatT: cols [Wl1|Wr1|Wres1|0], K=1024, tf32
__global__ void packWcatTKernel(const float* __restrict__ Wl1,
                                const float* __restrict__ Wr1,
                                const float* __restrict__ Wres1) {
    int i = blockIdx.x * 256 + threadIdx.x;
    if (i >= NKT1 * 4096) return;
    int kt = i >> 12;
    int p = i & 4095;
    int r = p >> 5, pos = p & 31;
    int chunk = (pos >> 2) ^ (r & 7);
    int ck = (chunk << 2) | (pos & 3);
    int kl = ((ck & 7) << 2) | (ck >> 3);
    int k = kt * 32 + kl;
    int n = r;
    float v = 0.f;
    if (n < HD1) v = Wl1[(size_t)k * HD1 + n];
    else if (n < 2 * HD1) v = Wr1[(size_t)k * HD1 + (n - HD1)];
    else if (n < L1W) v = Wres1[(size_t)k * HD1 + (n - 2 * HD1)];
    g_WcatT[i] = to_tf32(v);
}

// ------------------- CSR build ----------------------------------------------
__global__ void zeroKernel() {
    int i = blockIdx.x * 256 + threadIdx.x;
    if (i < NNODES) { g_deg[i] = 0; g_fill[i] = 0; }
}

__global__ void histKernel(const int* __restrict__ dst) {
    int e = blockIdx.x * 256 + threadIdx.x;
    if (e < NEDGES) atomicAdd(&g_deg[dst[e]], 1);
}

__global__ void scanKernel() {
    __shared__ int sums[1024];
    const int CH = (NNODES + 1023) / 1024;
    int t = threadIdx.x;
    int base = t * CH;
    int local[CH];
    int s = 0;
    for (int i = 0; i < CH; i++) {
        int v = (base + i < NNODES) ? g_deg[base + i] : 0;
        local[i] = s;
        s += v;
    }
    sums[t] = s;
    __syncthreads();
    for (int off = 1; off < 1024; off <<= 1) {
        int v = (t >= off) ? sums[t - off] : 0;
        __syncthreads();
        sums[t] += v;
        __syncthreads();
    }
    int excl = (t == 0) ? 0 : sums[t - 1];
    for (int i = 0; i < CH; i++)
        if (base + i < NNODES) g_csr_off[base + i] = excl + local[i];
    if (t == 1023) g_csr_off[NNODES] = sums[1023];
}

__global__ void fillCsrKernel(const int* __restrict__ dst) {
    int e = blockIdx.x * 256 + threadIdx.x;
    if (e >= NEDGES) return;
    int d = dst[e];
    int pos = atomicAdd(&g_fill[d], 1);
    g_csr_edge[g_csr_off[d] + pos] = e;
}

// ------------------- TF32 tensor GEMM on pre-packed tiles (R6, proven) -------
#define GEMM_SMEM (16384 * sizeof(float))

__global__ __launch_bounds__(256, 2) void tf32GemmKernel(
    const float* __restrict__ Apack, const float* __restrict__ Bpack,
    int nKt, float* __restrict__ C, int ldc, int Mrows, int Ncols) {
    extern __shared__ float sm[];
    int tid = threadIdx.x;
    int lane = tid & 31;
    int w = tid >> 5;
    int wm = w & 1, wn = w >> 1;
    int g = lane >> 2, tg = lane & 3;
    int r0 = blockIdx.x * 128, c0 = blockIdx.y * 128;

    const float* gA = Apack + ((size_t)blockIdx.x * nKt << 12);
    const float* gB = Bpack + ((size_t)blockIdx.y * nKt << 12);
    uint32_t sbase = (uint32_t)__cvta_generic_to_shared(sm);
    uint32_t sA[2] = {sbase, sbase + 16384u};
    uint32_t sB[2] = {sbase + 32768u, sbase + 49152u};

    float acc[4][4][4];
#pragma unroll
    for (int i = 0; i < 4; i++)
#pragma unroll
        for (int j = 0; j < 4; j++)
#pragma unroll
            for (int r = 0; r < 4; r++) acc[i][j][r] = 0.f;

#pragma unroll
    for (int s = 0; s < 4; s++) {
        int i = s * 256 + tid;
        cp16(sA[0] + i * 16, gA + i * 4);
        cp16(sB[0] + i * 16, gB + i * 4);
    }
    asm volatile("cp.async.commit_group;" ::: "memory");

    for (int kt = 0; kt < nKt; kt++) {
        int buf = kt & 1;
        bool hasNext = (kt + 1) < nKt;
        if (hasNext) {
            const float* nA = gA + ((size_t)(kt + 1) << 12);
            const float* nB = gB + ((size_t)(kt + 1) << 12);
            int nb = buf ^ 1;
#pragma unroll
            for (int s = 0; s < 4; s++) {
                int i = s * 256 + tid;
                cp16(sA[nb] + i * 16, nA + i * 4);
                cp16(sB[nb] + i * 16, nB + i * 4);
            }
            asm volatile("cp.async.commit_group;" ::: "memory");
            asm volatile("cp.async.wait_group 1;" ::: "memory");
        } else {
            asm volatile("cp.async.wait_group 0;" ::: "memory");
        }
        __syncthreads();

        const float* As = sm + (buf ? 4096 : 0);
        const float* Bs = sm + 8192 + (buf ? 4096 : 0);
#pragma unroll
        for (int half = 0; half < 2; half++) {
            int chunk = ((tg << 1) + half) ^ g;
            int coff = chunk << 2;
            float4 Af0[4], Af1[4], Bf[4];
#pragma unroll
            for (int mf = 0; mf < 4; mf++) {
                int r = wm * 64 + mf * 16 + g;
                Af0[mf] = *(const float4*)(As + (r << 5) + coff);
                Af1[mf] = *(const float4*)(As + ((r + 8) << 5) + coff);
            }
#pragma unroll
            for (int nf = 0; nf < 4; nf++) {
                int cc = wn * 32 + nf * 8 + g;
                Bf[nf] = *(const float4*)(Bs + (cc << 5) + coff);
            }
#pragma unroll
            for (int ks2 = 0; ks2 < 2; ks2++) {
#pragma unroll
                for (int mf = 0; mf < 4; mf++) {
                    uint32_t a0, a1, a2, a3;
                    if (ks2 == 0) {
                        a0 = fau(Af0[mf].x); a1 = fau(Af1[mf].x);
                        a2 = fau(Af0[mf].y); a3 = fau(Af1[mf].y);
                    } else {
                        a0 = fau(Af0[mf].z); a1 = fau(Af1[mf].z);
                        a2 = fau(Af0[mf].w); a3 = fau(Af1[mf].w);
                    }
#pragma unroll
                    for (int nf = 0; nf < 4; nf++) {
                        uint32_t b0 = (ks2 == 0) ? fau(Bf[nf].x) : fau(Bf[nf].z);
                        uint32_t b1 = (ks2 == 0) ? fau(Bf[nf].y) : fau(Bf[nf].w);
                        asm volatile(
                            "mma.sync.aligned.m16n8k8.row.col.f32.tf32.tf32.f32 "
                            "{%0,%1,%2,%3}, {%4,%5,%6,%7}, {%8,%9}, {%0,%1,%2,%3};"
                            : "+f"(acc[mf][nf][0]), "+f"(acc[mf][nf][1]),
                              "+f"(acc[mf][nf][2]), "+f"(acc[mf][nf][3])
                            : "r"(a0), "r"(a1), "r"(a2), "r"(a3),
                              "r"(b0), "r"(b1));
                    }
                }
            }
        }
        __syncthreads();
    }

#pragma unroll
    for (int mf = 0; mf < 4; mf++) {
        int rA = r0 + wm * 64 + mf * 16 + g;
        int rB = rA + 8;
#pragma unroll
        for (int nf = 0; nf < 4; nf++) {
            int gc = c0 + wn * 32 + nf * 8 + tg * 2;
            if (gc < Ncols) {
                if (rA < Mrows) C[(size_t)rA * ldc + gc] = acc[mf][nf][0];
                if (rB < Mrows) C[(size_t)rB * ldc + gc] = acc[mf][nf][2];
            }
            if (gc + 1 < Ncols) {
                if (rA < Mrows) C[(size_t)rA * ldc + gc + 1] = acc[mf][nf][1];
                if (rB < Mrows) C[(size_t)rB * ldc + gc + 1] = acc[mf][nf][3];
            }
        }
    }
}

// ------------------- gat_inner (h3) ------------------------------------------
__global__ void innerNodeTermsKernel(const float* __restrict__ a2) {
    int idx = blockIdx.x * 256 + threadIdx.x;
    if (idx >= NNODES * NH) return;
    int n = idx / NH, h = idx % NH;
    const float* z = g_big + (size_t)n * NBIG + 3 * HD0 + h * DD1;
    float es = 0.f, ed = 0.f;
#pragma unroll
    for (int o = 0; o < DD1; o++) {
        es = fmaf(z[o], a2[h * 2 * DD1 + o], es);
        ed = fmaf(z[o], a2[h * 2 * DD1 + DD1 + o], ed);
    }
    g_es2[idx] = es;
    g_ed2[idx] = ed;
}

// fused: compute inner logits + segment softmax (unnormalized) + den
__global__ void innerSoftmaxKernel(const int* __restrict__ src) {
    int idx = blockIdx.x * 256 + threadIdx.x;
    if (idx >= NNODES * NH) return;
    int n = idx / NH, h = idx % NH;
    int s = g_csr_off[n], t = g_csr_off[n + 1];
    float edv = g_ed2[idx];                 // dst term constant per segment
    float m = -1e30f;
    for (int p = s; p < t; p++) {
        int e = g_csr_edge[p];
        float l = lrelu(g_es2[src[e] * NH + h] + edv);
        g_lg2[e * NH + h] = l;
        m = fmaxf(m, l);
    }
    float den = 0.f;
    for (int p = s; p < t; p++) {
        int a = g_csr_edge[p] * NH + h;
        float pv = __expf(g_lg2[a] - m);
        den += pv;
        g_lg2[a] = pv;
    }
    g_den[idx] = fmaxf(den, 1e-9f);
}

// segment softmax over precomputed logits: leaves p unnormalized, writes den
__global__ void segSoftmaxKernel(float* __restrict__ lg) {
    int idx = blockIdx.x * 256 + threadIdx.x;
    if (idx >= NNODES * NH) return;
    int n = idx / NH, h = idx % NH;
    int s = g_csr_off[n], t = g_csr_off[n + 1];
    float m = -1e30f;
    for (int p = s; p < t; p++) m = fmaxf(m, lg[g_csr_edge[p] * NH + h]);
    float den = 0.f;
    for (int p = s; p < t; p++) {
        int a = g_csr_edge[p] * NH + h;
        float pv = __expf(lg[a] - m);
        den += pv;
        lg[a] = pv;
    }
    g_den[idx] = fmaxf(den, 1e-9f);
}

// warp-per-node aggregation for 32-wide values; divides by den
__global__ void aggSmallKernel(const float* __restrict__ vals, int vstride,
                               const float* __restrict__ lg,
                               const int* __restrict__ src,
                               const float* __restrict__ res, int rstride,
                               const float* __restrict__ bias,
                               float* __restrict__ out, int doRelu) {
    int w = (blockIdx.x * blockDim.x + threadIdx.x) >> 5;
    int lane = threadIdx.x & 31;
    if (w >= NNODES) return;
    int h = lane >> 3;
    int s = g_csr_off[w], t = g_csr_off[w + 1];
    float acc = 0.f;
    for (int p = s; p < t; p++) {
        int e = g_csr_edge[p];
        acc = fmaf(lg[e * NH + h], vals[(size_t)src[e] * vstride + lane], acc);
    }
    acc *= 1.f / g_den[w * NH + h];
    if (res) acc += res[(size_t)w * rstride + lane] + bias[lane];
    if (doRelu) acc = fmaxf(acc, 0.f);
    out[w * HD1 + lane] = acc;
}

// ------------------- gatv2 layer 0 (D=256) ------------------------------------
__global__ void gatv2EdgeLogits0Kernel(const int* __restrict__ src,
                                       const int* __restrict__ dst,
                                       const float* __restrict__ a0) {
    int e = blockIdx.x;
    int t = threadIdx.x;  // 128
    const float4* fs = (const float4*)(g_big + (size_t)src[e] * NBIG);
    const float4* fd = (const float4*)(g_big + (size_t)dst[e] * NBIG + HD0);
    const float4* a4 = (const float4*)a0;
    float partial = 0.f;
#pragma unroll
    for (int q = 0; q < 2; q++) {
        int i4 = t * 2 + q;
        float4 u = fs[i4], v = fd[i4], w = a4[i4];
        partial = fmaf(lrelu(u.x + v.x), w.x, partial);
        partial = fmaf(lrelu(u.y + v.y), w.y, partial);
        partial = fmaf(lrelu(u.z + v.z), w.z, partial);
        partial = fmaf(lrelu(u.w + v.w), w.w, partial);
    }
    for (int off = 16; off; off >>= 1)
        partial += __shfl_down_sync(0xffffffffu, partial, off);
    if ((t & 31) == 0) g_lg0[e * NH + (t >> 5)] = partial;
}

// aggregate layer-0 (unnormalized p, divide by den), residual+bias+relu;
// emit x1 as packed tf32 tiles
__global__ void gatv2Agg0Kernel(const int* __restrict__ src,
                                const float* __restrict__ b0) {
    int n = blockIdx.x;            // 0..MPAD-1
    int t = threadIdx.x;           // 256; 4 consecutive k each
    int r = n & 127, rt = n >> 7;
    float* base = g_x1A + ((size_t)rt * NKT1 << 12);
    if (n >= NNODES) {
#pragma unroll
        for (int q = 0; q < 4; q++) {
            int k = t * 4 + q;
            base[((k >> 5) << 12) + tileOff(r, k & 31)] = 0.f;
        }
        return;
    }
    int h = t >> 6;
    int s = g_csr_off[n], e1 = g_csr_off[n + 1];
    float4 acc = make_float4(0.f, 0.f, 0.f, 0.f);
    for (int p = s; p < e1; p++) {
        int e = g_csr_edge[p];
        float a = g_lg0[e * NH + h];
        float4 v = ((const float4*)(g_big + (size_t)src[e] * NBIG))[t];
        acc.x = fmaf(a, v.x, acc.x);
        acc.y = fmaf(a, v.y, acc.y);
        acc.z = fmaf(a, v.z, acc.z);
        acc.w = fmaf(a, v.w, acc.w);
    }
    float invd = 1.f / g_den[n * NH + h];
    float4 rr = ((const float4*)(g_big + (size_t)n * NBIG + 2 * HD0))[t];
    float4 bb = ((const float4*)b0)[t];
    float o[4];
    o[0] = fmaxf(acc.x * invd + rr.x + bb.x, 0.f);
    o[1] = fmaxf(acc.y * invd + rr.y + bb.y, 0.f);
    o[2] = fmaxf(acc.z * invd + rr.z + bb.z, 0.f);
    o[3] = fmaxf(acc.w * invd + rr.w + bb.w, 0.f);
#pragma unroll
    for (int q = 0; q < 4; q++) {
        int k = t * 4 + q;
        base[((k >> 5) << 12) + tileOff(r, k & 31)] = to_tf32(o[q]);
    }
}

// ------------------- gatv2 layer 1 (D=8) --------------------------------------
__global__ void gatv2EdgeLogits1Kernel(const int* __restrict__ src,
                                       const int* __restrict__ dst,
                                       const float* __restrict__ a1) {
    int w = (blockIdx.x * blockDim.x + threadIdx.x) >> 5;
    int lane = threadIdx.x & 31;
    if (w >= NEDGES) return;
    float x = g_l1out[(size_t)src[w] * L1W + lane] +
              g_l1out[(size_t)dst[w] * L1W + HD1 + lane];
    float p = lrelu(x) * a1[lane];
    p += __shfl_down_sync(0xffffffffu, p, 4, 8);
    p += __shfl_down_sync(0xffffffffu, p, 2, 8);
    p += __shfl_down_sync(0xffffffffu, p, 1, 8);
    if ((lane & 7) == 0) g_lg1[w * NH + (lane >> 3)] = p;
}

// ------------------- final linear ---------------------------------------------
__global__ void finalLinearKernel(const float* __restrict__ Wlin,
                                  const float* __restrict__ blin,
                                  float* __restrict__ out) {
    int n = blockIdx.x * 256 + threadIdx.x;
    if (n >= NNODES) return;
    float acc[OUTD];
#pragma unroll
    for (int c = 0; c < OUTD; c++) acc[c] = blin[c];
#pragma unroll 4
    for (int j = 0; j < HD1; j++) {
        float v = g_h3[n * HD1 + j];
#pragma unroll
        for (int c = 0; c < OUTD; c++) acc[c] = fmaf(v, Wlin[j * OUTD + c], acc[c]);
    }
#pragma unroll 4
    for (int j = 0; j < HD1; j++) {
        float v = g_out1[n * HD1 + j];
#pragma unroll
        for (int c = 0; c < OUTD; c++)
            acc[c] = fmaf(v, Wlin[(HD1 + j) * OUTD + c], acc[c]);
    }
#pragma unroll
    for (int c = 0; c < OUTD; c++) out[n * OUTD + c] = acc[c];
}

// ------------------- launch ---------------------------------------------------
extern "C" void kernel_launch(void* const* d_in, const int* in_sizes, int n_in,
                              void* d_out, int out_size) {
    const float* features = (const float*)d_in[0];
    const int* src = (const int*)d_in[1];
    const int* dst = (const int*)d_in[2];
    const float* textMask = (const float*)d_in[3];
    const float* audioMask = (const float*)d_in[4];
    const float* videoMask = (const float*)d_in[5];
    const float* W2 = (const float*)d_in[6];
    const float* a2 = (const float*)d_in[7];
    const float* Wl0 = (const float*)d_in[8];
    const float* Wr0 = (const float*)d_in[9];
    const float* a0 = (const float*)d_in[10];
    const float* Wres0 = (const float*)d_in[11];
    const float* b0 = (const float*)d_in[12];
    const float* Wl1 = (const float*)d_in[13];
    const float* Wr1 = (const float*)d_in[14];
    const float* a1 = (const float*)d_in[15];
    const float* Wres1 = (const float*)d_in[16];
    const float* b1 = (const float*)d_in[17];
    const float* Wlin = (const float*)d_in[18];
    const float* blin = (const float*)d_in[19];
    float* out = (float*)d_out;

    float *p_hA, *p_WbigT, *p_WcatT, *p_big, *p_x1A, *p_l1out;
    float *p_lg0, *p_lg1, *p_lg2, *p_h3, *p_out1;
    cudaGetSymbolAddress((void**)&p_hA, g_hA);
    cudaGetSymbolAddress((void**)&p_WbigT, g_WbigT);
    cudaGetSymbolAddress((void**)&p_WcatT, g_WcatT);
    cudaGetSymbolAddress((void**)&p_big, g_big);
    cudaGetSymbolAddress((void**)&p_x1A, g_x1A);
    cudaGetSymbolAddress((void**)&p_l1out, g_l1out);
    cudaGetSymbolAddress((void**)&p_lg0, g_lg0);
    cudaGetSymbolAddress((void**)&p_lg1, g_lg1);
    cudaGetSymbolAddress((void**)&p_lg2, g_lg2);
    cudaGetSymbolAddress((void**)&p_h3, g_h3);
    cudaGetSymbolAddress((void**)&p_out1, g_out1);

    cudaFuncSetAttribute(tf32GemmKernel,
                         cudaFuncAttributeMaxDynamicSharedMemorySize,
                         (int)GEMM_SMEM);

    // 1-3) preprocessing (launch #4 = big GEMM for the ncu capture slot)
    colsumKernel<<<(IN_DIM + 31) / 32, 256>>>(features);
    preprocessKernel<<<MPAD, 256>>>(features, textMask, audioMask, videoMask);
    packWbigTKernel<<<(NCT0 * NKT0 * 4096 + 255) / 256, 256>>>(Wl0, Wr0, Wres0, W2);

    // 4) fused big GEMM: [10112 x 1280] x [1280 x 3200] -> g_big [10000 x 3104]
    {
        dim3 g(NRT, NCT0);
        tf32GemmKernel<<<g, 256, GEMM_SMEM>>>(p_hA, p_WbigT, NKT0, p_big, NBIG,
                                              NNODES, NBIG);
    }

    // 5+) layer-1 weight pack + CSR build
    packWcatTKernel<<<(NKT1 * 4096 + 255) / 256, 256>>>(Wl1, Wr1, Wres1);
    zeroKernel<<<(NNODES + 255) / 256, 256>>>();
    histKernel<<<(NEDGES + 255) / 256, 256>>>(dst);
    scanKernel<<<1, 1024>>>();
    fillCsrKernel<<<(NEDGES + 255) / 256, 256>>>(dst);

    // gat_inner -> h3 (z2 = g_big cols 3072..3103)
    innerNodeTermsKernel<<<(NNODES * NH + 255) / 256, 256>>>(a2);
    innerSoftmaxKernel<<<(NNODES * NH + 255) / 256, 256>>>(src);
    aggSmallKernel<<<(NNODES * 32 + 255) / 256, 256>>>(p_big + 3 * HD0, NBIG, p_lg2,
                                                       src, (const float*)0, 0,
                                                       (const float*)0, p_h3, 0);

    // gatv2 layer 0 -> x1 (packed tiles)
    gatv2EdgeLogits0Kernel<<<NEDGES, 128>>>(src, dst, a0);
    segSoftmaxKernel<<<(NNODES * NH + 255) / 256, 256>>>(p_lg0);
    gatv2Agg0Kernel<<<MPAD, 256>>>(src, b0);

    // layer-1 projections: [10112 x 1024] x [1024 x 128] -> g_l1out [10000 x 96]
    {
        dim3 g(NRT, 1);
        tf32GemmKernel<<<g, 256, GEMM_SMEM>>>(p_x1A, p_WcatT, NKT1, p_l1out, L1W,
                                              NNODES, L1W);
    }

    // gatv2 layer 1 -> out1
    gatv2EdgeLogits1Kernel<<<(NEDGES * 32 + 255) / 256, 256>>>(src, dst, a1);
    segSoftmaxKernel<<<(NNODES * NH + 255) / 256, 256>>>(p_lg1);
    aggSmallKernel<<<(NNODES * 32 + 255) / 256, 256>>>(p_l1out, L1W, p_lg1, src,
                                                       p_l1out + 2 * HD1, L1W, b1,
                                                       p_out1, 1);

    // final linear
    finalLinearKernel<<<(NNODES + 255) / 256, 256>>>(Wlin, blin, out);
}